// round 5
// baseline (speedup 1.0000x reference)
#include <cuda_runtime.h>
#include <cuda_bf16.h>
#include <cstdint>

#define NNODES 50000
#define NEDGES 600000
#define C_IN   128
#define C_HID  128
#define C_OUT  40
#define NB     ((NNODES + 255) / 256)   /* 196 scan blocks */
#define KS     136                       /* smem k-major stride (conflict-free) */

// ---------------- scratch (static device globals; no allocation) -------------
__device__ float g_h1  [NNODES * C_HID];   // x@W1
__device__ float g_h1b [NNODES * C_HID];   // layer-1 output (post relu)
__device__ float g_h2  [NNODES * C_OUT];   // h1b@W2
__device__ float g_dinv[NNODES];
__device__ int   g_degi[NNODES];           // zero-initialized; re-zeroed by scan
__device__ int   g_rowstart[NNODES + 1];
__device__ int   g_cursor[NNODES];
__device__ int   g_csr_src[NEDGES];
__device__ float g_csr_nrm[NEDGES];
// decoupled-lookback scan state (zero-initialized; reset by csrfill each run)
__device__ int                g_ticket;
__device__ unsigned long long g_packed[NB];   // (flag<<32)|value, flag: 1=agg, 2=prefix

// ---------------- tf32 helpers -----------------------------------------------
__device__ __forceinline__ uint32_t f2tf32(float f) {
    uint32_t u;
    asm("cvt.rna.tf32.f32 %0, %1;" : "=r"(u) : "f"(f));
    return u;
}
__device__ __forceinline__ void mma_tf32(
    float& d0, float& d1, float& d2, float& d3,
    uint32_t a0, uint32_t a1, uint32_t a2, uint32_t a3,
    uint32_t b0, uint32_t b1)
{
    asm volatile(
        "mma.sync.aligned.m16n8k8.row.col.f32.tf32.tf32.f32 "
        "{%0,%1,%2,%3}, {%4,%5,%6,%7}, {%8,%9}, {%0,%1,%2,%3};"
        : "+f"(d0), "+f"(d1), "+f"(d2), "+f"(d3)
        : "r"(a0), "r"(a1), "r"(a2), "r"(a3), "r"(b0), "r"(b1));
}

// ---------------- degree ------------------------------------------------------
__global__ void degree_kernel(const int* __restrict__ ei) {
    int e = blockIdx.x * blockDim.x + threadIdx.x;
    if (e < NEDGES) atomicAdd(&g_degi[ei[NEDGES + e]], 1);
}

// ---------------- fused scan: dinv + rowstart + cursor, one launch ------------
__global__ __launch_bounds__(256) void scan_fused_kernel() {
    __shared__ int s[256];
    __shared__ int sh_bid;
    __shared__ int sh_prefix;

    int t = threadIdx.x;
    if (t == 0) sh_bid = atomicAdd(&g_ticket, 1);
    __syncthreads();
    int b   = sh_bid;
    int gid = b * 256 + t;

    int d = (gid < NNODES) ? g_degi[gid] : 0;
    if (gid < NNODES) {
        g_dinv[gid] = rsqrtf((float)d + 1.0f);
        g_degi[gid] = 0;                       // reset for next replay
    }
    s[t] = d;
    __syncthreads();
#pragma unroll
    for (int off = 1; off < 256; off <<= 1) {
        int v = (t >= off) ? s[t - off] : 0;
        __syncthreads();
        if (t >= off) s[t] += v;
        __syncthreads();
    }
    int incl = s[t];
    int aggregate = s[255];

    if (t == 0) {
        // publish aggregate
        atomicExch(&g_packed[b], (1ULL << 32) | (unsigned)aggregate);
        // lookback
        long long run = 0;
        int p = b - 1;
        while (p >= 0) {
            unsigned long long v;
            do { v = *((volatile unsigned long long*)&g_packed[p]); }
            while ((v >> 32) == 0ULL);
            run += (long long)(unsigned)v;
            if ((v >> 32) == 2ULL) break;
            --p;
        }
        // publish inclusive prefix
        atomicExch(&g_packed[b], (2ULL << 32) | (unsigned)(run + aggregate));
        sh_prefix = (int)run;
    }
    __syncthreads();

    if (gid < NNODES) {
        int r = sh_prefix + incl - d;          // global exclusive prefix
        g_rowstart[gid] = r;
        g_cursor[gid]   = r;
    }
    if (gid == 0) g_rowstart[NNODES] = NEDGES;
}

// ---------------- CSR fill (also resets scan state for next replay) ----------
__global__ void csrfill_kernel(const int* __restrict__ ei) {
    int e = blockIdx.x * blockDim.x + threadIdx.x;
    if (e < NB)  g_packed[e] = 0ULL;           // stream-ordered after scan grid
    if (e == NB) g_ticket = 0;
    if (e >= NEDGES) return;
    int s = ei[e];
    int d = ei[NEDGES + e];
    int pos = atomicAdd(&g_cursor[d], 1);
    g_csr_src[pos] = s;
    g_csr_nrm[pos] = g_dinv[s] * g_dinv[d];
}

// ---------------- tf32 GEMM: [M,128] @ [128,128] -> [M,128] --------------------
__global__ __launch_bounds__(256) void gemm128_tf32_kernel(
    const float* __restrict__ A, const float* __restrict__ W,
    float* __restrict__ C, int M)
{
    __shared__ uint32_t xs[32 * KS];
    __shared__ uint32_t ws[32 * KS];

    int tid  = threadIdx.x;
    int w    = tid >> 5;
    int lane = tid & 31;
    int g    = lane >> 2;
    int t4   = lane & 3;
    int r0   = blockIdx.x * 128;

    float acc[16][4];
#pragma unroll
    for (int j = 0; j < 16; j++)
#pragma unroll
        for (int i = 0; i < 4; i++) acc[j][i] = 0.f;

    for (int k0 = 0; k0 < 128; k0 += 32) {
#pragma unroll
        for (int L = tid; L < 1024; L += 256) {
            int r  = L >> 3;
            int kg = L & 7;
            int row = r0 + r;
            float4 v = make_float4(0.f, 0.f, 0.f, 0.f);
            if (row < M)
                v = *(const float4*)&A[(size_t)row * 128 + k0 + kg * 4];
            xs[(kg * 4 + 0) * KS + r] = f2tf32(v.x);
            xs[(kg * 4 + 1) * KS + r] = f2tf32(v.y);
            xs[(kg * 4 + 2) * KS + r] = f2tf32(v.z);
            xs[(kg * 4 + 3) * KS + r] = f2tf32(v.w);
        }
#pragma unroll
        for (int L = tid; L < 1024; L += 256) {
            int k  = L >> 5;
            int cg = L & 31;
            float4 v = *(const float4*)&W[(size_t)(k0 + k) * 128 + cg * 4];
            uint32_t* p = &ws[k * KS + cg * 4];
            p[0] = f2tf32(v.x);
            p[1] = f2tf32(v.y);
            p[2] = f2tf32(v.z);
            p[3] = f2tf32(v.w);
        }
        __syncthreads();

#pragma unroll
        for (int kt = 0; kt < 4; kt++) {
            int kr = kt * 8 + t4;
            uint32_t a0 = xs[kr * KS       + w * 16 + g];
            uint32_t a1 = xs[kr * KS       + w * 16 + g + 8];
            uint32_t a2 = xs[(kr + 4) * KS + w * 16 + g];
            uint32_t a3 = xs[(kr + 4) * KS + w * 16 + g + 8];
#pragma unroll
            for (int j = 0; j < 16; j++) {
                uint32_t b0 = ws[kr * KS       + j * 8 + g];
                uint32_t b1 = ws[(kr + 4) * KS + j * 8 + g];
                mma_tf32(acc[j][0], acc[j][1], acc[j][2], acc[j][3],
                         a0, a1, a2, a3, b0, b1);
            }
        }
        __syncthreads();
    }

    int rowA = r0 + w * 16 + g;
#pragma unroll
    for (int j = 0; j < 16; j++) {
        if (rowA < M)
            *(float2*)&C[(size_t)rowA * 128 + j * 8 + t4 * 2] =
                make_float2(acc[j][0], acc[j][1]);
        if (rowA + 8 < M)
            *(float2*)&C[(size_t)(rowA + 8) * 128 + j * 8 + t4 * 2] =
                make_float2(acc[j][2], acc[j][3]);
    }
}

// ---------------- tf32 GEMM: [M,128] @ [128,40] -> [M,40] ----------------------
__global__ __launch_bounds__(256) void gemm40_tf32_kernel(
    const float* __restrict__ A, const float* __restrict__ W,
    float* __restrict__ C, int M)
{
    __shared__ uint32_t xs[32 * KS];
    __shared__ uint32_t ws[32 * KS];

    int tid  = threadIdx.x;
    int w    = tid >> 5;
    int lane = tid & 31;
    int g    = lane >> 2;
    int t4   = lane & 3;
    int r0   = blockIdx.x * 128;

    float acc[5][4];
#pragma unroll
    for (int j = 0; j < 5; j++)
#pragma unroll
        for (int i = 0; i < 4; i++) acc[j][i] = 0.f;

    for (int k0 = 0; k0 < 128; k0 += 32) {
#pragma unroll
        for (int L = tid; L < 1024; L += 256) {
            int r  = L >> 3;
            int kg = L & 7;
            int row = r0 + r;
            float4 v = make_float4(0.f, 0.f, 0.f, 0.f);
            if (row < M)
                v = *(const float4*)&A[(size_t)row * 128 + k0 + kg * 4];
            xs[(kg * 4 + 0) * KS + r] = f2tf32(v.x);
            xs[(kg * 4 + 1) * KS + r] = f2tf32(v.y);
            xs[(kg * 4 + 2) * KS + r] = f2tf32(v.z);
            xs[(kg * 4 + 3) * KS + r] = f2tf32(v.w);
        }
        for (int L = tid; L < 320; L += 256) {
            int k  = L / 10;
            int cg = L % 10;
            float4 v = *(const float4*)&W[(size_t)(k0 + k) * 40 + cg * 4];
            uint32_t* p = &ws[k * KS + cg * 4];
            p[0] = f2tf32(v.x);
            p[1] = f2tf32(v.y);
            p[2] = f2tf32(v.z);
            p[3] = f2tf32(v.w);
        }
        __syncthreads();

#pragma unroll
        for (int kt = 0; kt < 4; kt++) {
            int kr = kt * 8 + t4;
            uint32_t a0 = xs[kr * KS       + w * 16 + g];
            uint32_t a1 = xs[kr * KS       + w * 16 + g + 8];
            uint32_t a2 = xs[(kr + 4) * KS + w * 16 + g];
            uint32_t a3 = xs[(kr + 4) * KS + w * 16 + g + 8];
#pragma unroll
            for (int j = 0; j < 5; j++) {
                uint32_t b0 = ws[kr * KS       + j * 8 + g];
                uint32_t b1 = ws[(kr + 4) * KS + j * 8 + g];
                mma_tf32(acc[j][0], acc[j][1], acc[j][2], acc[j][3],
                         a0, a1, a2, a3, b0, b1);
            }
        }
        __syncthreads();
    }

    int rowA = r0 + w * 16 + g;
#pragma unroll
    for (int j = 0; j < 5; j++) {
        if (rowA < M)
            *(float2*)&C[(size_t)rowA * 40 + j * 8 + t4 * 2] =
                make_float2(acc[j][0], acc[j][1]);
        if (rowA + 8 < M)
            *(float2*)&C[(size_t)(rowA + 8) * 40 + j * 8 + t4 * 2] =
                make_float2(acc[j][2], acc[j][3]);
    }
}

// ---------------- gather layer 1 (C=128): warp per node, 4x unroll ------------
__global__ __launch_bounds__(256) void gather128_kernel(const float* __restrict__ b1) {
    int w = (blockIdx.x * blockDim.x + threadIdx.x) >> 5;
    if (w >= NNODES) return;
    int lane = threadIdx.x & 31;

    int start = g_rowstart[w];
    int end   = g_rowstart[w + 1];

    const float4* __restrict__ h = (const float4*)g_h1;
    float4 acc = make_float4(0.f, 0.f, 0.f, 0.f);

    int j = start;
    for (; j + 3 < end; j += 4) {
        int   s0 = __ldg(&g_csr_src[j]);
        int   s1 = __ldg(&g_csr_src[j + 1]);
        int   s2 = __ldg(&g_csr_src[j + 2]);
        int   s3 = __ldg(&g_csr_src[j + 3]);
        float n0 = __ldg(&g_csr_nrm[j]);
        float n1 = __ldg(&g_csr_nrm[j + 1]);
        float n2 = __ldg(&g_csr_nrm[j + 2]);
        float n3 = __ldg(&g_csr_nrm[j + 3]);
        float4 v0 = h[(size_t)s0 * 32 + lane];
        float4 v1 = h[(size_t)s1 * 32 + lane];
        float4 v2 = h[(size_t)s2 * 32 + lane];
        float4 v3 = h[(size_t)s3 * 32 + lane];
        acc.x = fmaf(n0, v0.x, acc.x); acc.y = fmaf(n0, v0.y, acc.y);
        acc.z = fmaf(n0, v0.z, acc.z); acc.w = fmaf(n0, v0.w, acc.w);
        acc.x = fmaf(n1, v1.x, acc.x); acc.y = fmaf(n1, v1.y, acc.y);
        acc.z = fmaf(n1, v1.z, acc.z); acc.w = fmaf(n1, v1.w, acc.w);
        acc.x = fmaf(n2, v2.x, acc.x); acc.y = fmaf(n2, v2.y, acc.y);
        acc.z = fmaf(n2, v2.z, acc.z); acc.w = fmaf(n2, v2.w, acc.w);
        acc.x = fmaf(n3, v3.x, acc.x); acc.y = fmaf(n3, v3.y, acc.y);
        acc.z = fmaf(n3, v3.z, acc.z); acc.w = fmaf(n3, v3.w, acc.w);
    }
    for (; j < end; ++j) {
        int   s0 = __ldg(&g_csr_src[j]);
        float n0 = __ldg(&g_csr_nrm[j]);
        float4 v0 = h[(size_t)s0 * 32 + lane];
        acc.x = fmaf(n0, v0.x, acc.x); acc.y = fmaf(n0, v0.y, acc.y);
        acc.z = fmaf(n0, v0.z, acc.z); acc.w = fmaf(n0, v0.w, acc.w);
    }

    float di = g_dinv[w];
    float d2 = di * di;
    float4 hv = h[(size_t)w * 32 + lane];
    float4 bb = ((const float4*)b1)[lane];
    float4 r;
    r.x = fmaxf(fmaf(hv.x, d2, acc.x) + bb.x, 0.f);
    r.y = fmaxf(fmaf(hv.y, d2, acc.y) + bb.y, 0.f);
    r.z = fmaxf(fmaf(hv.z, d2, acc.z) + bb.z, 0.f);
    r.w = fmaxf(fmaf(hv.w, d2, acc.w) + bb.w, 0.f);
    ((float4*)g_h1b)[(size_t)w * 32 + lane] = r;
}

// ---------------- gather layer 2 (C=40): two nodes per warp, 4x unroll --------
__global__ __launch_bounds__(256) void gather40_kernel(const float* __restrict__ b2,
                                                       float* __restrict__ out) {
    int w = (blockIdx.x * blockDim.x + threadIdx.x) >> 5;
    int lane = threadIdx.x & 31;
    int node = w * 2 + (lane >> 4);
    if (node >= NNODES) return;
    int sub = lane & 15;
    bool active = sub < 10;

    int start = g_rowstart[node];
    int end   = g_rowstart[node + 1];

    const float4* __restrict__ h = (const float4*)g_h2;
    float4 acc = make_float4(0.f, 0.f, 0.f, 0.f);

    int j = start;
    for (; j + 3 < end; j += 4) {
        int   s0 = __ldg(&g_csr_src[j]);
        int   s1 = __ldg(&g_csr_src[j + 1]);
        int   s2 = __ldg(&g_csr_src[j + 2]);
        int   s3 = __ldg(&g_csr_src[j + 3]);
        float n0 = __ldg(&g_csr_nrm[j]);
        float n1 = __ldg(&g_csr_nrm[j + 1]);
        float n2 = __ldg(&g_csr_nrm[j + 2]);
        float n3 = __ldg(&g_csr_nrm[j + 3]);
        if (active) {
            float4 v0 = h[(size_t)s0 * 10 + sub];
            float4 v1 = h[(size_t)s1 * 10 + sub];
            float4 v2 = h[(size_t)s2 * 10 + sub];
            float4 v3 = h[(size_t)s3 * 10 + sub];
            acc.x = fmaf(n0, v0.x, acc.x); acc.y = fmaf(n0, v0.y, acc.y);
            acc.z = fmaf(n0, v0.z, acc.z); acc.w = fmaf(n0, v0.w, acc.w);
            acc.x = fmaf(n1, v1.x, acc.x); acc.y = fmaf(n1, v1.y, acc.y);
            acc.z = fmaf(n1, v1.z, acc.z); acc.w = fmaf(n1, v1.w, acc.w);
            acc.x = fmaf(n2, v2.x, acc.x); acc.y = fmaf(n2, v2.y, acc.y);
            acc.z = fmaf(n2, v2.z, acc.z); acc.w = fmaf(n2, v2.w, acc.w);
            acc.x = fmaf(n3, v3.x, acc.x); acc.y = fmaf(n3, v3.y, acc.y);
            acc.z = fmaf(n3, v3.z, acc.z); acc.w = fmaf(n3, v3.w, acc.w);
        }
    }
    for (; j < end; ++j) {
        int   s0 = __ldg(&g_csr_src[j]);
        float n0 = __ldg(&g_csr_nrm[j]);
        if (active) {
            float4 v0 = h[(size_t)s0 * 10 + sub];
            acc.x = fmaf(n0, v0.x, acc.x); acc.y = fmaf(n0, v0.y, acc.y);
            acc.z = fmaf(n0, v0.z, acc.z); acc.w = fmaf(n0, v0.w, acc.w);
        }
    }

    if (active) {
        float di = g_dinv[node];
        float d2 = di * di;
        float4 hv = h[(size_t)node * 10 + sub];
        float4 bb = ((const float4*)b2)[sub];
        float4 r;
        r.x = fmaf(hv.x, d2, acc.x) + bb.x;
        r.y = fmaf(hv.y, d2, acc.y) + bb.y;
        r.z = fmaf(hv.z, d2, acc.z) + bb.z;
        r.w = fmaf(hv.w, d2, acc.w) + bb.w;
        ((float4*)out)[(size_t)node * 10 + sub] = r;
    }
}

// -----------------------------------------------------------------------------
extern "C" void kernel_launch(void* const* d_in, const int* in_sizes, int n_in,
                              void* d_out, int out_size) {
    const float* x   = (const float*)d_in[0];
    const int*   ei  = (const int*)  d_in[1];
    const float* W1  = (const float*)d_in[2];
    const float* b1  = (const float*)d_in[3];
    const float* W2  = (const float*)d_in[4];
    const float* b2  = (const float*)d_in[5];
    float* out = (float*)d_out;

    float* h1_p;  cudaGetSymbolAddress((void**)&h1_p,  g_h1);
    float* h1b_p; cudaGetSymbolAddress((void**)&h1b_p, g_h1b);
    float* h2_p;  cudaGetSymbolAddress((void**)&h2_p,  g_h2);

    // ---- CSR build: 3 launches ----
    degree_kernel<<<(NEDGES + 255) / 256, 256>>>(ei);
    scan_fused_kernel<<<NB, 256>>>();
    csrfill_kernel<<<(NEDGES + 255) / 256, 256>>>(ei);

    // ---- layer 1 ----
    gemm128_tf32_kernel<<<(NNODES + 127) / 128, 256>>>(x, W1, h1_p, NNODES);
    gather128_kernel<<<(NNODES * 32 + 255) / 256, 256>>>(b1);

    // ---- layer 2 ----
    gemm40_tf32_kernel<<<(NNODES + 127) / 128, 256>>>(h1b_p, W2, h2_p, NNODES);
    gather40_kernel<<<((NNODES + 1) / 2 * 32 + 255) / 256, 256>>>(b2, out);
}

// round 6
// speedup vs baseline: 1.3102x; 1.3102x over previous
#include <cuda_runtime.h>
#include <cuda_fp16.h>
#include <cstdint>

#define NNODES 50000
#define NEDGES 600000
#define NB     ((NNODES + 255) / 256)   /* 196 scan blocks */
#define KS2    136                       /* smem half2 stride (frag-conflict-free) */

// ---------------- scratch (static device globals; no allocation) -------------
__device__ __align__(16) uint32_t g_h1h [NNODES * 64];  // x@W1, half2 packed
__device__ __align__(16) uint32_t g_h1bh[NNODES * 64];  // relu layer-1 out, half2
__device__ __align__(16) uint32_t g_h2h [NNODES * 20];  // h1b@W2, half2
__device__ float g_dinv[NNODES];
__device__ int   g_degi[NNODES];           // zero-init; re-zeroed by scan
__device__ int   g_rowstart[NNODES + 1];
__device__ int   g_cursor[NNODES];
__device__ int   g_csr_src[NEDGES];
__device__ float g_csr_nrm[NEDGES];
// decoupled-lookback state (zero-init; reset by csrfill each replay)
__device__ int                g_ticket;
__device__ unsigned long long g_packed[NB];  // (flag<<32)|value; 1=agg, 2=prefix

// ---------------- helpers ------------------------------------------------------
__device__ __forceinline__ uint32_t pkh2(float a, float b) {
    __half2 h = __floats2half2_rn(a, b);
    return *reinterpret_cast<uint32_t*>(&h);
}
__device__ __forceinline__ float2 h2f2(uint32_t u) {
    __half2 h = *reinterpret_cast<__half2*>(&u);
    return __half22float2(h);
}
__device__ __forceinline__ void mma_f16(
    float& d0, float& d1, float& d2, float& d3,
    uint32_t a0, uint32_t a1, uint32_t a2, uint32_t a3,
    uint32_t b0, uint32_t b1)
{
    asm volatile(
        "mma.sync.aligned.m16n8k16.row.col.f32.f16.f16.f32 "
        "{%0,%1,%2,%3}, {%4,%5,%6,%7}, {%8,%9}, {%0,%1,%2,%3};"
        : "+f"(d0), "+f"(d1), "+f"(d2), "+f"(d3)
        : "r"(a0), "r"(a1), "r"(a2), "r"(a3), "r"(b0), "r"(b1));
}

// ---------------- degree ------------------------------------------------------
__global__ void degree_kernel(const int* __restrict__ ei) {
    int e = blockIdx.x * blockDim.x + threadIdx.x;
    if (e < NEDGES) atomicAdd(&g_degi[ei[NEDGES + e]], 1);
}

// ---------------- fused scan: dinv + rowstart + cursor (warp lookback) --------
__global__ __launch_bounds__(256) void scan_fused_kernel() {
    __shared__ int s[256];
    __shared__ int sh_bid;
    __shared__ int sh_prefix;

    int t = threadIdx.x;
    if (t == 0) sh_bid = atomicAdd(&g_ticket, 1);
    __syncthreads();
    int b   = sh_bid;
    int gid = b * 256 + t;

    int d = (gid < NNODES) ? g_degi[gid] : 0;
    if (gid < NNODES) {
        g_dinv[gid] = rsqrtf((float)d + 1.0f);
        g_degi[gid] = 0;                       // reset for next replay
    }
    s[t] = d;
    __syncthreads();
#pragma unroll
    for (int off = 1; off < 256; off <<= 1) {
        int v = (t >= off) ? s[t - off] : 0;
        __syncthreads();
        if (t >= off) s[t] += v;
        __syncthreads();
    }
    int incl = s[t];
    int aggregate = s[255];

    if (t == 0)
        atomicExch(&g_packed[b], (1ULL << 32) | (unsigned)aggregate);

    if (t < 32) {   // warp 0: parallel lookback, 32 predecessors per step
        int run = 0;
        int p = b - 1;
        while (p >= 0) {
            int idx = p - t;
            unsigned long long v = 0ULL;
            if (idx >= 0) {
                do { v = *((volatile unsigned long long*)&g_packed[idx]); }
                while ((v >> 32) == 0ULL);
            }
            unsigned flag = (unsigned)(v >> 32);
            unsigned val  = (unsigned)v;
            unsigned ball = __ballot_sync(0xffffffffu, flag == 2u);
            int lp = ball ? (__ffs(ball) - 1) : 32;
            if (t > lp) val = 0;
#pragma unroll
            for (int o = 16; o; o >>= 1)
                val += __shfl_xor_sync(0xffffffffu, val, o);
            run += (int)val;
            if (ball) break;
            p -= 32;
        }
        if (t == 0) {
            atomicExch(&g_packed[b], (2ULL << 32) | (unsigned)(run + aggregate));
            sh_prefix = run;
        }
    }
    __syncthreads();

    if (gid < NNODES) {
        int r = sh_prefix + incl - d;          // global exclusive prefix
        g_rowstart[gid] = r;
        g_cursor[gid]   = r;
    }
    if (gid == 0) g_rowstart[NNODES] = NEDGES;
}

// ---------------- CSR fill (also resets scan state for next replay) ----------
__global__ void csrfill_kernel(const int* __restrict__ ei) {
    int e = blockIdx.x * blockDim.x + threadIdx.x;
    if (e < NB)  g_packed[e] = 0ULL;
    if (e == NB) g_ticket = 0;
    if (e >= NEDGES) return;
    int s = ei[e];
    int d = ei[NEDGES + e];
    int pos = atomicAdd(&g_cursor[d], 1);
    g_csr_src[pos] = s;
    g_csr_nrm[pos] = g_dinv[s] * g_dinv[d];
}

// ---------------- fp16 GEMM: [M,128]fp32 @ [128,128]fp32 -> half2 -------------
// Tile 128x128, 8 warps x (16 rows x 128 cols), K-tile 32, m16n8k16.
__global__ __launch_bounds__(256) void gemm128_f16_kernel(
    const float* __restrict__ A, const float* __restrict__ W,
    uint32_t* __restrict__ C, int M)
{
    __shared__ uint32_t xs[16 * KS2];   // [k2][row] half2 over (k,k+1)
    __shared__ uint32_t ws[16 * KS2];   // [k2][col] half2 over (k,k+1)

    int tid  = threadIdx.x;
    int w    = tid >> 5;
    int lane = tid & 31;
    int g    = lane >> 2;
    int t4   = lane & 3;
    int r0   = blockIdx.x * 128;

    float acc[16][4];
#pragma unroll
    for (int j = 0; j < 16; j++)
#pragma unroll
        for (int i = 0; i < 4; i++) acc[j][i] = 0.f;

    for (int k0 = 0; k0 < 128; k0 += 32) {
        // A tile: 128 rows x 8 float4 groups
#pragma unroll
        for (int L = tid; L < 1024; L += 256) {
            int r  = L >> 3;
            int kg = L & 7;
            int row = r0 + r;
            float4 v = make_float4(0.f, 0.f, 0.f, 0.f);
            if (row < M)
                v = *(const float4*)&A[(size_t)row * 128 + k0 + kg * 4];
            xs[(kg * 2 + 0) * KS2 + r] = pkh2(v.x, v.y);
            xs[(kg * 2 + 1) * KS2 + r] = pkh2(v.z, v.w);
        }
        // W tile: 16 k2 x 32 col-groups; pack (k even, k odd) pairs
#pragma unroll
        for (int L = tid; L < 512; L += 256) {
            int k2 = L >> 5;
            int cg = L & 31;
            float4 lo = *(const float4*)&W[(size_t)(k0 + 2 * k2)     * 128 + cg * 4];
            float4 hi = *(const float4*)&W[(size_t)(k0 + 2 * k2 + 1) * 128 + cg * 4];
            uint4* p4 = (uint4*)&ws[k2 * KS2 + cg * 4];
            *p4 = make_uint4(pkh2(lo.x, hi.x), pkh2(lo.y, hi.y),
                             pkh2(lo.z, hi.z), pkh2(lo.w, hi.w));
        }
        __syncthreads();

#pragma unroll
        for (int kt = 0; kt < 2; kt++) {
            int kr = kt * 8 + t4;
            uint32_t a0 = xs[kr * KS2       + w * 16 + g];
            uint32_t a1 = xs[kr * KS2       + w * 16 + g + 8];
            uint32_t a2 = xs[(kr + 4) * KS2 + w * 16 + g];
            uint32_t a3 = xs[(kr + 4) * KS2 + w * 16 + g + 8];
#pragma unroll
            for (int j = 0; j < 16; j++) {
                uint32_t b0 = ws[kr * KS2       + j * 8 + g];
                uint32_t b1 = ws[(kr + 4) * KS2 + j * 8 + g];
                mma_f16(acc[j][0], acc[j][1], acc[j][2], acc[j][3],
                        a0, a1, a2, a3, b0, b1);
            }
        }
        __syncthreads();
    }

    int rowA = r0 + w * 16 + g;
#pragma unroll
    for (int j = 0; j < 16; j++) {
        if (rowA < M)
            C[(size_t)rowA * 64 + j * 4 + t4] = pkh2(acc[j][0], acc[j][1]);
        if (rowA + 8 < M)
            C[(size_t)(rowA + 8) * 64 + j * 4 + t4] = pkh2(acc[j][2], acc[j][3]);
    }
}

// ---------------- fp16 GEMM: [M,128]half @ [128,40]fp32 -> half2 --------------
__global__ __launch_bounds__(256) void gemm40_f16_kernel(
    const uint32_t* __restrict__ Ah, const float* __restrict__ W,
    uint32_t* __restrict__ C, int M)
{
    __shared__ uint32_t xs[16 * KS2];
    __shared__ uint32_t ws[16 * KS2];

    int tid  = threadIdx.x;
    int w    = tid >> 5;
    int lane = tid & 31;
    int g    = lane >> 2;
    int t4   = lane & 3;
    int r0   = blockIdx.x * 128;

    float acc[5][4];
#pragma unroll
    for (int j = 0; j < 5; j++)
#pragma unroll
        for (int i = 0; i < 4; i++) acc[j][i] = 0.f;

    for (int k0 = 0; k0 < 128; k0 += 32) {
        // A tile (already half2): 128 rows x 4 uint4 groups (8 halves each)
#pragma unroll
        for (int L = tid; L < 512; L += 256) {
            int r  = L >> 2;
            int kq = L & 3;
            int row = r0 + r;
            uint4 v = make_uint4(0u, 0u, 0u, 0u);
            if (row < M)
                v = *(const uint4*)&Ah[(size_t)row * 64 + k0 / 2 + kq * 4];
            xs[(kq * 4 + 0) * KS2 + r] = v.x;
            xs[(kq * 4 + 1) * KS2 + r] = v.y;
            xs[(kq * 4 + 2) * KS2 + r] = v.z;
            xs[(kq * 4 + 3) * KS2 + r] = v.w;
        }
        // W tile: 16 k2 x 10 col-groups
        for (int L = tid; L < 160; L += 256) {
            int k2 = L >> 4 /*?*/ ;
            int cg;
            k2 = L / 10; cg = L % 10;
            float4 lo = *(const float4*)&W[(size_t)(k0 + 2 * k2)     * 40 + cg * 4];
            float4 hi = *(const float4*)&W[(size_t)(k0 + 2 * k2 + 1) * 40 + cg * 4];
            uint4* p4 = (uint4*)&ws[k2 * KS2 + cg * 4];
            *p4 = make_uint4(pkh2(lo.x, hi.x), pkh2(lo.y, hi.y),
                             pkh2(lo.z, hi.z), pkh2(lo.w, hi.w));
        }
        __syncthreads();

#pragma unroll
        for (int kt = 0; kt < 2; kt++) {
            int kr = kt * 8 + t4;
            uint32_t a0 = xs[kr * KS2       + w * 16 + g];
            uint32_t a1 = xs[kr * KS2       + w * 16 + g + 8];
            uint32_t a2 = xs[(kr + 4) * KS2 + w * 16 + g];
            uint32_t a3 = xs[(kr + 4) * KS2 + w * 16 + g + 8];
#pragma unroll
            for (int j = 0; j < 5; j++) {
                uint32_t b0 = ws[kr * KS2       + j * 8 + g];
                uint32_t b1 = ws[(kr + 4) * KS2 + j * 8 + g];
                mma_f16(acc[j][0], acc[j][1], acc[j][2], acc[j][3],
                        a0, a1, a2, a3, b0, b1);
            }
        }
        __syncthreads();
    }

    int rowA = r0 + w * 16 + g;
#pragma unroll
    for (int j = 0; j < 5; j++) {
        if (rowA < M)
            C[(size_t)rowA * 20 + j * 4 + t4] = pkh2(acc[j][0], acc[j][1]);
        if (rowA + 8 < M)
            C[(size_t)(rowA + 8) * 20 + j * 4 + t4] = pkh2(acc[j][2], acc[j][3]);
    }
}

// ---------------- gather layer 1 (C=128, fp16): warp per node -----------------
__global__ __launch_bounds__(256) void gather128_kernel(const float* __restrict__ b1) {
    int w = (blockIdx.x * blockDim.x + threadIdx.x) >> 5;
    if (w >= NNODES) return;
    int lane = threadIdx.x & 31;

    int start = g_rowstart[w];
    int end   = g_rowstart[w + 1];

    const uint2* __restrict__ h = (const uint2*)g_h1h;   // 4 halves per lane
    float4 acc = make_float4(0.f, 0.f, 0.f, 0.f);

    int j = start;
    for (; j + 3 < end; j += 4) {
        int   s0 = __ldg(&g_csr_src[j]);
        int   s1 = __ldg(&g_csr_src[j + 1]);
        int   s2 = __ldg(&g_csr_src[j + 2]);
        int   s3 = __ldg(&g_csr_src[j + 3]);
        float n0 = __ldg(&g_csr_nrm[j]);
        float n1 = __ldg(&g_csr_nrm[j + 1]);
        float n2 = __ldg(&g_csr_nrm[j + 2]);
        float n3 = __ldg(&g_csr_nrm[j + 3]);
        uint2 u0 = h[(size_t)s0 * 32 + lane];
        uint2 u1 = h[(size_t)s1 * 32 + lane];
        uint2 u2 = h[(size_t)s2 * 32 + lane];
        uint2 u3 = h[(size_t)s3 * 32 + lane];
        float2 a, b;
        a = h2f2(u0.x); b = h2f2(u0.y);
        acc.x = fmaf(n0, a.x, acc.x); acc.y = fmaf(n0, a.y, acc.y);
        acc.z = fmaf(n0, b.x, acc.z); acc.w = fmaf(n0, b.y, acc.w);
        a = h2f2(u1.x); b = h2f2(u1.y);
        acc.x = fmaf(n1, a.x, acc.x); acc.y = fmaf(n1, a.y, acc.y);
        acc.z = fmaf(n1, b.x, acc.z); acc.w = fmaf(n1, b.y, acc.w);
        a = h2f2(u2.x); b = h2f2(u2.y);
        acc.x = fmaf(n2, a.x, acc.x); acc.y = fmaf(n2, a.y, acc.y);
        acc.z = fmaf(n2, b.x, acc.z); acc.w = fmaf(n2, b.y, acc.w);
        a = h2f2(u3.x); b = h2f2(u3.y);
        acc.x = fmaf(n3, a.x, acc.x); acc.y = fmaf(n3, a.y, acc.y);
        acc.z = fmaf(n3, b.x, acc.z); acc.w = fmaf(n3, b.y, acc.w);
    }
    for (; j < end; ++j) {
        int   s0 = __ldg(&g_csr_src[j]);
        float n0 = __ldg(&g_csr_nrm[j]);
        uint2 u0 = h[(size_t)s0 * 32 + lane];
        float2 a = h2f2(u0.x), b = h2f2(u0.y);
        acc.x = fmaf(n0, a.x, acc.x); acc.y = fmaf(n0, a.y, acc.y);
        acc.z = fmaf(n0, b.x, acc.z); acc.w = fmaf(n0, b.y, acc.w);
    }

    float di = g_dinv[w];
    float d2 = di * di;
    uint2 us = h[(size_t)w * 32 + lane];
    float2 ha = h2f2(us.x), hb = h2f2(us.y);
    float4 bb = ((const float4*)b1)[lane];
    float rx = fmaxf(fmaf(ha.x, d2, acc.x) + bb.x, 0.f);
    float ry = fmaxf(fmaf(ha.y, d2, acc.y) + bb.y, 0.f);
    float rz = fmaxf(fmaf(hb.x, d2, acc.z) + bb.z, 0.f);
    float rw = fmaxf(fmaf(hb.y, d2, acc.w) + bb.w, 0.f);
    uint2 o;
    o.x = pkh2(rx, ry);
    o.y = pkh2(rz, rw);
    ((uint2*)g_h1bh)[(size_t)w * 32 + lane] = o;
}

// ---------------- gather layer 2 (C=40, fp16): two nodes per warp -------------
__global__ __launch_bounds__(256) void gather40_kernel(const float* __restrict__ b2,
                                                       float* __restrict__ out) {
    int w = (blockIdx.x * blockDim.x + threadIdx.x) >> 5;
    int lane = threadIdx.x & 31;
    int node = w * 2 + (lane >> 4);
    if (node >= NNODES) return;
    int sub = lane & 15;
    bool active = sub < 10;

    int start = g_rowstart[node];
    int end   = g_rowstart[node + 1];

    const uint2* __restrict__ h = (const uint2*)g_h2h;   // 4 halves per lane
    float4 acc = make_float4(0.f, 0.f, 0.f, 0.f);

    int j = start;
    for (; j + 3 < end; j += 4) {
        int   s0 = __ldg(&g_csr_src[j]);
        int   s1 = __ldg(&g_csr_src[j + 1]);
        int   s2 = __ldg(&g_csr_src[j + 2]);
        int   s3 = __ldg(&g_csr_src[j + 3]);
        float n0 = __ldg(&g_csr_nrm[j]);
        float n1 = __ldg(&g_csr_nrm[j + 1]);
        float n2 = __ldg(&g_csr_nrm[j + 2]);
        float n3 = __ldg(&g_csr_nrm[j + 3]);
        if (active) {
            uint2 u0 = h[(size_t)s0 * 10 + sub];
            uint2 u1 = h[(size_t)s1 * 10 + sub];
            uint2 u2 = h[(size_t)s2 * 10 + sub];
            uint2 u3 = h[(size_t)s3 * 10 + sub];
            float2 a, b;
            a = h2f2(u0.x); b = h2f2(u0.y);
            acc.x = fmaf(n0, a.x, acc.x); acc.y = fmaf(n0, a.y, acc.y);
            acc.z = fmaf(n0, b.x, acc.z); acc.w = fmaf(n0, b.y, acc.w);
            a = h2f2(u1.x); b = h2f2(u1.y);
            acc.x = fmaf(n1, a.x, acc.x); acc.y = fmaf(n1, a.y, acc.y);
            acc.z = fmaf(n1, b.x, acc.z); acc.w = fmaf(n1, b.y, acc.w);
            a = h2f2(u2.x); b = h2f2(u2.y);
            acc.x = fmaf(n2, a.x, acc.x); acc.y = fmaf(n2, a.y, acc.y);
            acc.z = fmaf(n2, b.x, acc.z); acc.w = fmaf(n2, b.y, acc.w);
            a = h2f2(u3.x); b = h2f2(u3.y);
            acc.x = fmaf(n3, a.x, acc.x); acc.y = fmaf(n3, a.y, acc.y);
            acc.z = fmaf(n3, b.x, acc.z); acc.w = fmaf(n3, b.y, acc.w);
        }
    }
    for (; j < end; ++j) {
        int   s0 = __ldg(&g_csr_src[j]);
        float n0 = __ldg(&g_csr_nrm[j]);
        if (active) {
            uint2 u0 = h[(size_t)s0 * 10 + sub];
            float2 a = h2f2(u0.x), b = h2f2(u0.y);
            acc.x = fmaf(n0, a.x, acc.x); acc.y = fmaf(n0, a.y, acc.y);
            acc.z = fmaf(n0, b.x, acc.z); acc.w = fmaf(n0, b.y, acc.w);
        }
    }

    if (active) {
        float di = g_dinv[node];
        float d2 = di * di;
        uint2 us = h[(size_t)node * 10 + sub];
        float2 ha = h2f2(us.x), hb = h2f2(us.y);
        float4 bb = ((const float4*)b2)[sub];
        float4 r;
        r.x = fmaf(ha.x, d2, acc.x) + bb.x;
        r.y = fmaf(ha.y, d2, acc.y) + bb.y;
        r.z = fmaf(hb.x, d2, acc.z) + bb.z;
        r.w = fmaf(hb.y, d2, acc.w) + bb.w;
        *(float4*)&out[(size_t)node * 40 + sub * 4] = r;
    }
}

// -----------------------------------------------------------------------------
extern "C" void kernel_launch(void* const* d_in, const int* in_sizes, int n_in,
                              void* d_out, int out_size) {
    const float* x   = (const float*)d_in[0];
    const int*   ei  = (const int*)  d_in[1];
    const float* W1  = (const float*)d_in[2];
    const float* b1  = (const float*)d_in[3];
    const float* W2  = (const float*)d_in[4];
    const float* b2  = (const float*)d_in[5];
    float* out = (float*)d_out;

    uint32_t* h1_p;  cudaGetSymbolAddress((void**)&h1_p,  g_h1h);
    uint32_t* h1b_p; cudaGetSymbolAddress((void**)&h1b_p, g_h1bh);
    uint32_t* h2_p;  cudaGetSymbolAddress((void**)&h2_p,  g_h2h);

    // ---- CSR build: 3 launches ----
    degree_kernel<<<(NEDGES + 255) / 256, 256>>>(ei);
    scan_fused_kernel<<<NB, 256>>>();
    csrfill_kernel<<<(NEDGES + 255) / 256, 256>>>(ei);

    // ---- layer 1 ----
    gemm128_f16_kernel<<<(NNODES + 127) / 128, 256>>>(x, W1, h1_p, NNODES);
    gather128_kernel<<<(NNODES * 32 + 255) / 256, 256>>>(b1);

    // ---- layer 2 ----
    gemm40_f16_kernel<<<(NNODES + 127) / 128, 256>>>(h1b_p, W2, h2_p, NNODES);
    gather40_kernel<<<((NNODES + 1) / 2 * 32 + 255) / 256, 256>>>(b2, out);
}

// round 7
// speedup vs baseline: 1.4016x; 1.0698x over previous
#include <cuda_runtime.h>
#include <cuda_fp16.h>
#include <cstdint>

#define NNODES 50000
#define NEDGES 600000
#define NB     ((NNODES + 255) / 256)   /* 196 scan blocks */
#define KS2    136   /* ws k2-major stride: bank = t4*8+g, conflict-free */
#define SR     68    /* xs row-major stride: bank = g*4+t4, conflict-free */
#define GEMM_SMEM ((128 * SR + 64 * KS2) * 4)   /* 69632 bytes */

// ---------------- scratch (static device globals; no allocation) -------------
__device__ __align__(16) uint32_t g_h1h [NNODES * 64];  // x@W1, half2 packed
__device__ __align__(16) uint32_t g_h1bh[NNODES * 64];  // relu layer-1 out, half2
__device__ __align__(16) uint32_t g_h2h [NNODES * 20];  // h1b@W2, half2
__device__ float g_dinv[NNODES];
__device__ int   g_degi[NNODES];           // zero-init; re-zeroed by scan
__device__ int   g_rowstart[NNODES + 1];
__device__ int   g_cursor[NNODES];
__device__ int   g_csr_src[NEDGES];
__device__ float g_csr_nrm[NEDGES];
// decoupled-lookback state (zero-init; reset by csrfill each replay)
__device__ int                g_ticket;
__device__ unsigned long long g_packed[NB];  // (flag<<32)|value; 1=agg, 2=prefix

// ---------------- helpers ------------------------------------------------------
__device__ __forceinline__ uint32_t pkh2(float a, float b) {
    __half2 h = __floats2half2_rn(a, b);
    return *reinterpret_cast<uint32_t*>(&h);
}
__device__ __forceinline__ float2 h2f2(uint32_t u) {
    __half2 h = *reinterpret_cast<__half2*>(&u);
    return __half22float2(h);
}
__device__ __forceinline__ void mma_f16(
    float& d0, float& d1, float& d2, float& d3,
    uint32_t a0, uint32_t a1, uint32_t a2, uint32_t a3,
    uint32_t b0, uint32_t b1)
{
    asm volatile(
        "mma.sync.aligned.m16n8k16.row.col.f32.f16.f16.f32 "
        "{%0,%1,%2,%3}, {%4,%5,%6,%7}, {%8,%9}, {%0,%1,%2,%3};"
        : "+f"(d0), "+f"(d1), "+f"(d2), "+f"(d3)
        : "r"(a0), "r"(a1), "r"(a2), "r"(a3), "r"(b0), "r"(b1));
}

// ---------------- degree ------------------------------------------------------
__global__ void degree_kernel(const int* __restrict__ ei) {
    int e = blockIdx.x * blockDim.x + threadIdx.x;
    if (e < NEDGES) atomicAdd(&g_degi[ei[NEDGES + e]], 1);
}

// ---------------- fused scan: dinv + rowstart + cursor (warp lookback) --------
__global__ __launch_bounds__(256) void scan_fused_kernel() {
    __shared__ int s[256];
    __shared__ int sh_bid;
    __shared__ int sh_prefix;

    int t = threadIdx.x;
    if (t == 0) sh_bid = atomicAdd(&g_ticket, 1);
    __syncthreads();
    int b   = sh_bid;
    int gid = b * 256 + t;

    int d = (gid < NNODES) ? g_degi[gid] : 0;
    if (gid < NNODES) {
        g_dinv[gid] = rsqrtf((float)d + 1.0f);
        g_degi[gid] = 0;                       // reset for next replay
    }
    s[t] = d;
    __syncthreads();
#pragma unroll
    for (int off = 1; off < 256; off <<= 1) {
        int v = (t >= off) ? s[t - off] : 0;
        __syncthreads();
        if (t >= off) s[t] += v;
        __syncthreads();
    }
    int incl = s[t];
    int aggregate = s[255];

    if (t == 0)
        atomicExch(&g_packed[b], (1ULL << 32) | (unsigned)aggregate);

    if (t < 32) {   // warp 0: parallel lookback, 32 predecessors per step
        int run = 0;
        int p = b - 1;
        while (p >= 0) {
            int idx = p - t;
            unsigned long long v = 0ULL;
            if (idx >= 0) {
                do { v = *((volatile unsigned long long*)&g_packed[idx]); }
                while ((v >> 32) == 0ULL);
            }
            unsigned flag = (unsigned)(v >> 32);
            unsigned val  = (unsigned)v;
            unsigned ball = __ballot_sync(0xffffffffu, flag == 2u);
            int lp = ball ? (__ffs(ball) - 1) : 32;
            if (t > lp) val = 0;
#pragma unroll
            for (int o = 16; o; o >>= 1)
                val += __shfl_xor_sync(0xffffffffu, val, o);
            run += (int)val;
            if (ball) break;
            p -= 32;
        }
        if (t == 0) {
            atomicExch(&g_packed[b], (2ULL << 32) | (unsigned)(run + aggregate));
            sh_prefix = run;
        }
    }
    __syncthreads();

    if (gid < NNODES) {
        int r = sh_prefix + incl - d;          // global exclusive prefix
        g_rowstart[gid] = r;
        g_cursor[gid]   = r;
    }
    if (gid == 0) g_rowstart[NNODES] = NEDGES;
}

// ---------------- CSR fill (also resets scan state for next replay) ----------
__global__ void csrfill_kernel(const int* __restrict__ ei) {
    int e = blockIdx.x * blockDim.x + threadIdx.x;
    if (e < NB)  g_packed[e] = 0ULL;
    if (e == NB) g_ticket = 0;
    if (e >= NEDGES) return;
    int s = ei[e];
    int d = ei[NEDGES + e];
    int pos = atomicAdd(&g_cursor[d], 1);
    g_csr_src[pos] = s;
    g_csr_nrm[pos] = g_dinv[s] * g_dinv[d];
}

// ---------------- single-shot fp16 GEMM: [M,128]f32 @ [128,128]f32 -> half2 ---
// Whole A-tile and whole W resident in smem; ONE sync; 128 MMAs per warp.
__global__ __launch_bounds__(256) void gemm128_f16_kernel(
    const float* __restrict__ A, const float* __restrict__ W,
    uint32_t* __restrict__ C, int M)
{
    extern __shared__ uint32_t sm[];
    uint32_t* xs = sm;             // [row 0..127][k2 0..63]  stride SR
    uint32_t* ws = sm + 128 * SR;  // [k2 0..63][col 0..127]  stride KS2

    int tid  = threadIdx.x;
    int w    = tid >> 5;
    int lane = tid & 31;
    int g    = lane >> 2;
    int t4   = lane & 3;
    int r0   = blockIdx.x * 128;

    // A: 128 rows x 32 float4 groups; gmem fully coalesced, smem uint2 stores
#pragma unroll
    for (int L = tid; L < 4096; L += 256) {
        int r  = L >> 5;
        int kg = L & 31;
        int row = r0 + r;
        float4 v = make_float4(0.f, 0.f, 0.f, 0.f);
        if (row < M)
            v = *(const float4*)&A[(size_t)row * 128 + kg * 4];
        *(uint2*)&xs[r * SR + kg * 2] = make_uint2(pkh2(v.x, v.y), pkh2(v.z, v.w));
    }
    // W: 64 k2 x 32 col-groups; pack (k even, k odd)
#pragma unroll
    for (int L = tid; L < 2048; L += 256) {
        int k2 = L >> 5;
        int cg = L & 31;
        float4 lo = *(const float4*)&W[(size_t)(2 * k2)     * 128 + cg * 4];
        float4 hi = *(const float4*)&W[(size_t)(2 * k2 + 1) * 128 + cg * 4];
        *(uint4*)&ws[k2 * KS2 + cg * 4] =
            make_uint4(pkh2(lo.x, hi.x), pkh2(lo.y, hi.y),
                       pkh2(lo.z, hi.z), pkh2(lo.w, hi.w));
    }
    __syncthreads();

    float acc[16][4];
#pragma unroll
    for (int j = 0; j < 16; j++)
#pragma unroll
        for (int i = 0; i < 4; i++) acc[j][i] = 0.f;

    int rb = (w * 16 + g) * SR;
#pragma unroll
    for (int m = 0; m < 8; m++) {
        int kr = m * 8 + t4;
        uint32_t a0 = xs[rb            + kr - m * 8 + m * 8];   // row g,   k2 kr
        a0 = xs[rb + kr];
        uint32_t a1 = xs[rb + 8 * SR + kr];                     // row g+8, k2 kr
        uint32_t a2 = xs[rb + kr + 4];                          // row g,   k2 kr+4
        uint32_t a3 = xs[rb + 8 * SR + kr + 4];                 // row g+8, k2 kr+4
#pragma unroll
        for (int j = 0; j < 16; j++) {
            uint32_t b0 = ws[kr * KS2       + j * 8 + g];
            uint32_t b1 = ws[(kr + 4) * KS2 + j * 8 + g];
            mma_f16(acc[j][0], acc[j][1], acc[j][2], acc[j][3],
                    a0, a1, a2, a3, b0, b1);
        }
    }

    int rowA = r0 + w * 16 + g;
#pragma unroll
    for (int j = 0; j < 16; j++) {
        if (rowA < M)
            C[(size_t)rowA * 64 + j * 4 + t4] = pkh2(acc[j][0], acc[j][1]);
        if (rowA + 8 < M)
            C[(size_t)(rowA + 8) * 64 + j * 4 + t4] = pkh2(acc[j][2], acc[j][3]);
    }
}

// ---------------- single-shot fp16 GEMM: [M,128]half @ [128,40]f32 -> half2 ---
__global__ __launch_bounds__(256) void gemm40_f16_kernel(
    const uint32_t* __restrict__ Ah, const float* __restrict__ W,
    uint32_t* __restrict__ C, int M)
{
    extern __shared__ uint32_t sm[];
    uint32_t* xs = sm;             // [row][k2] stride SR
    uint32_t* ws = sm + 128 * SR;  // [k2][col<40] stride KS2

    int tid  = threadIdx.x;
    int w    = tid >> 5;
    int lane = tid & 31;
    int g    = lane >> 2;
    int t4   = lane & 3;
    int r0   = blockIdx.x * 128;

    // A (already half2): 128 rows x 16 uint4 groups
#pragma unroll
    for (int L = tid; L < 2048; L += 256) {
        int r  = L >> 4;
        int kq = L & 15;
        int row = r0 + r;
        uint4 v = make_uint4(0u, 0u, 0u, 0u);
        if (row < M)
            v = *(const uint4*)&Ah[(size_t)row * 64 + kq * 4];
        *(uint4*)&xs[r * SR + kq * 4] = v;
    }
    // W: 64 k2 x 10 col-groups
    for (int L = tid; L < 640; L += 256) {
        int k2 = L / 10;
        int cg = L % 10;
        float4 lo = *(const float4*)&W[(size_t)(2 * k2)     * 40 + cg * 4];
        float4 hi = *(const float4*)&W[(size_t)(2 * k2 + 1) * 40 + cg * 4];
        *(uint4*)&ws[k2 * KS2 + cg * 4] =
            make_uint4(pkh2(lo.x, hi.x), pkh2(lo.y, hi.y),
                       pkh2(lo.z, hi.z), pkh2(lo.w, hi.w));
    }
    __syncthreads();

    float acc[5][4];
#pragma unroll
    for (int j = 0; j < 5; j++)
#pragma unroll
        for (int i = 0; i < 4; i++) acc[j][i] = 0.f;

    int rb = (w * 16 + g) * SR;
#pragma unroll
    for (int m = 0; m < 8; m++) {
        int kr = m * 8 + t4;
        uint32_t a0 = xs[rb            + kr];
        uint32_t a1 = xs[rb + 8 * SR + kr];
        uint32_t a2 = xs[rb            + kr + 4];
        uint32_t a3 = xs[rb + 8 * SR + kr + 4];
#pragma unroll
        for (int j = 0; j < 5; j++) {
            uint32_t b0 = ws[kr * KS2       + j * 8 + g];
            uint32_t b1 = ws[(kr + 4) * KS2 + j * 8 + g];
            mma_f16(acc[j][0], acc[j][1], acc[j][2], acc[j][3],
                    a0, a1, a2, a3, b0, b1);
        }
    }

    int rowA = r0 + w * 16 + g;
#pragma unroll
    for (int j = 0; j < 5; j++) {
        if (rowA < M)
            C[(size_t)rowA * 20 + j * 4 + t4] = pkh2(acc[j][0], acc[j][1]);
        if (rowA + 8 < M)
            C[(size_t)(rowA + 8) * 20 + j * 4 + t4] = pkh2(acc[j][2], acc[j][3]);
    }
}

// ---------------- gather layer 1 (C=128, fp16): warp per node -----------------
__global__ __launch_bounds__(256) void gather128_kernel(const float* __restrict__ b1) {
    int w = (blockIdx.x * blockDim.x + threadIdx.x) >> 5;
    if (w >= NNODES) return;
    int lane = threadIdx.x & 31;

    int start = g_rowstart[w];
    int end   = g_rowstart[w + 1];

    const uint2* __restrict__ h = (const uint2*)g_h1h;   // 4 halves per lane
    float4 acc = make_float4(0.f, 0.f, 0.f, 0.f);

    int j = start;
    for (; j + 3 < end; j += 4) {
        int   s0 = __ldg(&g_csr_src[j]);
        int   s1 = __ldg(&g_csr_src[j + 1]);
        int   s2 = __ldg(&g_csr_src[j + 2]);
        int   s3 = __ldg(&g_csr_src[j + 3]);
        float n0 = __ldg(&g_csr_nrm[j]);
        float n1 = __ldg(&g_csr_nrm[j + 1]);
        float n2 = __ldg(&g_csr_nrm[j + 2]);
        float n3 = __ldg(&g_csr_nrm[j + 3]);
        uint2 u0 = h[(size_t)s0 * 32 + lane];
        uint2 u1 = h[(size_t)s1 * 32 + lane];
        uint2 u2 = h[(size_t)s2 * 32 + lane];
        uint2 u3 = h[(size_t)s3 * 32 + lane];
        float2 a, b;
        a = h2f2(u0.x); b = h2f2(u0.y);
        acc.x = fmaf(n0, a.x, acc.x); acc.y = fmaf(n0, a.y, acc.y);
        acc.z = fmaf(n0, b.x, acc.z); acc.w = fmaf(n0, b.y, acc.w);
        a = h2f2(u1.x); b = h2f2(u1.y);
        acc.x = fmaf(n1, a.x, acc.x); acc.y = fmaf(n1, a.y, acc.y);
        acc.z = fmaf(n1, b.x, acc.z); acc.w = fmaf(n1, b.y, acc.w);
        a = h2f2(u2.x); b = h2f2(u2.y);
        acc.x = fmaf(n2, a.x, acc.x); acc.y = fmaf(n2, a.y, acc.y);
        acc.z = fmaf(n2, b.x, acc.z); acc.w = fmaf(n2, b.y, acc.w);
        a = h2f2(u3.x); b = h2f2(u3.y);
        acc.x = fmaf(n3, a.x, acc.x); acc.y = fmaf(n3, a.y, acc.y);
        acc.z = fmaf(n3, b.x, acc.z); acc.w = fmaf(n3, b.y, acc.w);
    }
    for (; j < end; ++j) {
        int   s0 = __ldg(&g_csr_src[j]);
        float n0 = __ldg(&g_csr_nrm[j]);
        uint2 u0 = h[(size_t)s0 * 32 + lane];
        float2 a = h2f2(u0.x), b = h2f2(u0.y);
        acc.x = fmaf(n0, a.x, acc.x); acc.y = fmaf(n0, a.y, acc.y);
        acc.z = fmaf(n0, b.x, acc.z); acc.w = fmaf(n0, b.y, acc.w);
    }

    float di = g_dinv[w];
    float d2 = di * di;
    uint2 us = h[(size_t)w * 32 + lane];
    float2 ha = h2f2(us.x), hb = h2f2(us.y);
    float4 bb = ((const float4*)b1)[lane];
    float rx = fmaxf(fmaf(ha.x, d2, acc.x) + bb.x, 0.f);
    float ry = fmaxf(fmaf(ha.y, d2, acc.y) + bb.y, 0.f);
    float rz = fmaxf(fmaf(hb.x, d2, acc.z) + bb.z, 0.f);
    float rw = fmaxf(fmaf(hb.y, d2, acc.w) + bb.w, 0.f);
    uint2 o;
    o.x = pkh2(rx, ry);
    o.y = pkh2(rz, rw);
    ((uint2*)g_h1bh)[(size_t)w * 32 + lane] = o;
}

// ---------------- gather layer 2 (C=40, fp16): two nodes per warp -------------
__global__ __launch_bounds__(256) void gather40_kernel(const float* __restrict__ b2,
                                                       float* __restrict__ out) {
    int w = (blockIdx.x * blockDim.x + threadIdx.x) >> 5;
    int lane = threadIdx.x & 31;
    int node = w * 2 + (lane >> 4);
    if (node >= NNODES) return;
    int sub = lane & 15;
    bool active = sub < 10;

    int start = g_rowstart[node];
    int end   = g_rowstart[node + 1];

    const uint2* __restrict__ h = (const uint2*)g_h2h;   // 4 halves per lane
    float4 acc = make_float4(0.f, 0.f, 0.f, 0.f);

    int j = start;
    for (; j + 3 < end; j += 4) {
        int   s0 = __ldg(&g_csr_src[j]);
        int   s1 = __ldg(&g_csr_src[j + 1]);
        int   s2 = __ldg(&g_csr_src[j + 2]);
        int   s3 = __ldg(&g_csr_src[j + 3]);
        float n0 = __ldg(&g_csr_nrm[j]);
        float n1 = __ldg(&g_csr_nrm[j + 1]);
        float n2 = __ldg(&g_csr_nrm[j + 2]);
        float n3 = __ldg(&g_csr_nrm[j + 3]);
        if (active) {
            uint2 u0 = h[(size_t)s0 * 10 + sub];
            uint2 u1 = h[(size_t)s1 * 10 + sub];
            uint2 u2 = h[(size_t)s2 * 10 + sub];
            uint2 u3 = h[(size_t)s3 * 10 + sub];
            float2 a, b;
            a = h2f2(u0.x); b = h2f2(u0.y);
            acc.x = fmaf(n0, a.x, acc.x); acc.y = fmaf(n0, a.y, acc.y);
            acc.z = fmaf(n0, b.x, acc.z); acc.w = fmaf(n0, b.y, acc.w);
            a = h2f2(u1.x); b = h2f2(u1.y);
            acc.x = fmaf(n1, a.x, acc.x); acc.y = fmaf(n1, a.y, acc.y);
            acc.z = fmaf(n1, b.x, acc.z); acc.w = fmaf(n1, b.y, acc.w);
            a = h2f2(u2.x); b = h2f2(u2.y);
            acc.x = fmaf(n2, a.x, acc.x); acc.y = fmaf(n2, a.y, acc.y);
            acc.z = fmaf(n2, b.x, acc.z); acc.w = fmaf(n2, b.y, acc.w);
            a = h2f2(u3.x); b = h2f2(u3.y);
            acc.x = fmaf(n3, a.x, acc.x); acc.y = fmaf(n3, a.y, acc.y);
            acc.z = fmaf(n3, b.x, acc.z); acc.w = fmaf(n3, b.y, acc.w);
        }
    }
    for (; j < end; ++j) {
        int   s0 = __ldg(&g_csr_src[j]);
        float n0 = __ldg(&g_csr_nrm[j]);
        if (active) {
            uint2 u0 = h[(size_t)s0 * 10 + sub];
            float2 a = h2f2(u0.x), b = h2f2(u0.y);
            acc.x = fmaf(n0, a.x, acc.x); acc.y = fmaf(n0, a.y, acc.y);
            acc.z = fmaf(n0, b.x, acc.z); acc.w = fmaf(n0, b.y, acc.w);
        }
    }

    if (active) {
        float di = g_dinv[node];
        float d2 = di * di;
        uint2 us = h[(size_t)node * 10 + sub];
        float2 ha = h2f2(us.x), hb = h2f2(us.y);
        float4 bb = ((const float4*)b2)[sub];
        float4 r;
        r.x = fmaf(ha.x, d2, acc.x) + bb.x;
        r.y = fmaf(ha.y, d2, acc.y) + bb.y;
        r.z = fmaf(hb.x, d2, acc.z) + bb.z;
        r.w = fmaf(hb.y, d2, acc.w) + bb.w;
        *(float4*)&out[(size_t)node * 40 + sub * 4] = r;
    }
}

// -----------------------------------------------------------------------------
extern "C" void kernel_launch(void* const* d_in, const int* in_sizes, int n_in,
                              void* d_out, int out_size) {
    const float* x   = (const float*)d_in[0];
    const int*   ei  = (const int*)  d_in[1];
    const float* W1  = (const float*)d_in[2];
    const float* b1  = (const float*)d_in[3];
    const float* W2  = (const float*)d_in[4];
    const float* b2  = (const float*)d_in[5];
    float* out = (float*)d_out;

    static bool s_init = false;
    if (!s_init) {   // host-side setup only; device work identical every call
        cudaFuncSetAttribute(gemm128_f16_kernel,
                             cudaFuncAttributeMaxDynamicSharedMemorySize, GEMM_SMEM);
        cudaFuncSetAttribute(gemm40_f16_kernel,
                             cudaFuncAttributeMaxDynamicSharedMemorySize, GEMM_SMEM);
        s_init = true;
    }

    uint32_t* h1_p;  cudaGetSymbolAddress((void**)&h1_p,  g_h1h);
    uint32_t* h1b_p; cudaGetSymbolAddress((void**)&h1b_p, g_h1bh);
    uint32_t* h2_p;  cudaGetSymbolAddress((void**)&h2_p,  g_h2h);

    // ---- CSR build: 3 launches ----
    degree_kernel<<<(NEDGES + 255) / 256, 256>>>(ei);
    scan_fused_kernel<<<NB, 256>>>();
    csrfill_kernel<<<(NEDGES + 255) / 256, 256>>>(ei);

    // ---- layer 1 ----
    gemm128_f16_kernel<<<(NNODES + 127) / 128, 256, GEMM_SMEM>>>(x, W1, h1_p, NNODES);
    gather128_kernel<<<(NNODES * 32 + 255) / 256, 256>>>(b1);

    // ---- layer 2 ----
    gemm40_f16_kernel<<<(NNODES + 127) / 128, 256, GEMM_SMEM>>>(h1b_p, W2, h2_p, NNODES);
    gather40_kernel<<<((NNODES + 1) / 2 * 32 + 255) / 256, 256>>>(b2, out);
}

// round 8
// speedup vs baseline: 1.4613x; 1.0426x over previous
#include <cuda_runtime.h>
#include <cuda_fp16.h>
#include <cstdint>

#define NNODES 50000
#define NEDGES 600000
#define NB     ((NNODES + 255) / 256)   /* 196 scan blocks */
#define SR     68    /* smem row stride in words: row starts quad-aligned banks */
#define GEMM_SMEM ((128 * SR + 128 * SR) * 4)   /* xs + wh = 69632 bytes */

// ---------------- scratch (static device globals; no allocation) -------------
__device__ __align__(16) uint32_t g_h1h [NNODES * 64];  // x@W1, half2 packed
__device__ __align__(16) uint32_t g_h1bh[NNODES * 64];  // relu layer-1 out, half2
__device__ __align__(16) uint32_t g_h2h [NNODES * 20];  // h1b@W2, half2
__device__ float g_dinv[NNODES];
__device__ int   g_degi[NNODES];           // zero-init; re-zeroed by scan
__device__ int   g_rowstart[NNODES + 1];
__device__ int   g_cursor[NNODES];
__device__ int   g_csr_src[NEDGES];
__device__ float g_csr_nrm[NEDGES];
// decoupled-lookback state (zero-init; reset by csrfill each replay)
__device__ int                g_ticket;
__device__ unsigned long long g_packed[NB];  // (flag<<32)|value; 1=agg, 2=prefix

// ---------------- helpers ------------------------------------------------------
__device__ __forceinline__ uint32_t pkh2(float a, float b) {
    __half2 h = __floats2half2_rn(a, b);
    return *reinterpret_cast<uint32_t*>(&h);
}
__device__ __forceinline__ float2 h2f2(uint32_t u) {
    __half2 h = *reinterpret_cast<__half2*>(&u);
    return __half22float2(h);
}
__device__ __forceinline__ void mma_f16(
    float& d0, float& d1, float& d2, float& d3,
    uint32_t a0, uint32_t a1, uint32_t a2, uint32_t a3,
    uint32_t b0, uint32_t b1)
{
    asm volatile(
        "mma.sync.aligned.m16n8k16.row.col.f32.f16.f16.f32 "
        "{%0,%1,%2,%3}, {%4,%5,%6,%7}, {%8,%9}, {%0,%1,%2,%3};"
        : "+f"(d0), "+f"(d1), "+f"(d2), "+f"(d3)
        : "r"(a0), "r"(a1), "r"(a2), "r"(a3), "r"(b0), "r"(b1));
}
__device__ __forceinline__ void ldsm_x4(
    uint32_t& r0, uint32_t& r1, uint32_t& r2, uint32_t& r3, uint32_t addr)
{
    asm volatile("ldmatrix.sync.aligned.m8n8.x4.shared.b16 {%0,%1,%2,%3}, [%4];"
        : "=r"(r0), "=r"(r1), "=r"(r2), "=r"(r3) : "r"(addr));
}
__device__ __forceinline__ void ldsm_x4t(
    uint32_t& r0, uint32_t& r1, uint32_t& r2, uint32_t& r3, uint32_t addr)
{
    asm volatile("ldmatrix.sync.aligned.m8n8.x4.trans.shared.b16 {%0,%1,%2,%3}, [%4];"
        : "=r"(r0), "=r"(r1), "=r"(r2), "=r"(r3) : "r"(addr));
}

// ---------------- degree ------------------------------------------------------
__global__ void degree_kernel(const int* __restrict__ ei) {
    int e = blockIdx.x * blockDim.x + threadIdx.x;
    if (e < NEDGES) atomicAdd(&g_degi[ei[NEDGES + e]], 1);
}

// ---------------- fused scan: dinv + rowstart + cursor (warp lookback) --------
__global__ __launch_bounds__(256) void scan_fused_kernel() {
    __shared__ int s[256];
    __shared__ int sh_bid;
    __shared__ int sh_prefix;

    int t = threadIdx.x;
    if (t == 0) sh_bid = atomicAdd(&g_ticket, 1);
    __syncthreads();
    int b   = sh_bid;
    int gid = b * 256 + t;

    int d = (gid < NNODES) ? g_degi[gid] : 0;
    if (gid < NNODES) {
        g_dinv[gid] = rsqrtf((float)d + 1.0f);
        g_degi[gid] = 0;                       // reset for next replay
    }
    s[t] = d;
    __syncthreads();
#pragma unroll
    for (int off = 1; off < 256; off <<= 1) {
        int v = (t >= off) ? s[t - off] : 0;
        __syncthreads();
        if (t >= off) s[t] += v;
        __syncthreads();
    }
    int incl = s[t];
    int aggregate = s[255];

    if (t == 0)
        atomicExch(&g_packed[b], (1ULL << 32) | (unsigned)aggregate);

    if (t < 32) {   // warp 0: parallel lookback
        int run = 0;
        int p = b - 1;
        while (p >= 0) {
            int idx = p - t;
            unsigned long long v = 0ULL;
            if (idx >= 0) {
                do { v = *((volatile unsigned long long*)&g_packed[idx]); }
                while ((v >> 32) == 0ULL);
            }
            unsigned flag = (unsigned)(v >> 32);
            unsigned val  = (unsigned)v;
            unsigned ball = __ballot_sync(0xffffffffu, flag == 2u);
            int lp = ball ? (__ffs(ball) - 1) : 32;
            if (t > lp) val = 0;
#pragma unroll
            for (int o = 16; o; o >>= 1)
                val += __shfl_xor_sync(0xffffffffu, val, o);
            run += (int)val;
            if (ball) break;
            p -= 32;
        }
        if (t == 0) {
            atomicExch(&g_packed[b], (2ULL << 32) | (unsigned)(run + aggregate));
            sh_prefix = run;
        }
    }
    __syncthreads();

    if (gid < NNODES) {
        int r = sh_prefix + incl - d;
        g_rowstart[gid] = r;
        g_cursor[gid]   = r;
    }
    if (gid == 0) g_rowstart[NNODES] = NEDGES;
}

// ---------------- CSR fill (also resets scan state for next replay) ----------
__global__ void csrfill_kernel(const int* __restrict__ ei) {
    int e = blockIdx.x * blockDim.x + threadIdx.x;
    if (e < NB)  g_packed[e] = 0ULL;
    if (e == NB) g_ticket = 0;
    if (e >= NEDGES) return;
    int s = ei[e];
    int d = ei[NEDGES + e];
    int pos = atomicAdd(&g_cursor[d], 1);
    g_csr_src[pos] = s;
    g_csr_nrm[pos] = g_dinv[s] * g_dinv[d];
}

// ---------------- single-shot fp16 GEMM (ldmatrix): [M,128] @ [128,128] -------
__global__ __launch_bounds__(256) void gemm128_f16_kernel(
    const float* __restrict__ A, const float* __restrict__ W,
    uint32_t* __restrict__ C, int M)
{
    extern __shared__ uint32_t sm[];
    uint32_t* xs = sm;             // [row 0..127][k2 0..63]  stride SR words
    uint32_t* wh = sm + 128 * SR;  // [k  0..127][n half2 0..63] stride SR words

    int tid  = threadIdx.x;
    int w    = tid >> 5;
    int lane = tid & 31;
    int g    = lane >> 2;
    int t4   = lane & 3;
    int r0   = blockIdx.x * 128;

    // A: 128 rows x 32 float4 groups; coalesced gmem, half2 smem
#pragma unroll
    for (int L = tid; L < 4096; L += 256) {
        int r  = L >> 5;
        int kg = L & 31;
        int row = r0 + r;
        float4 v = make_float4(0.f, 0.f, 0.f, 0.f);
        if (row < M)
            v = *(const float4*)&A[(size_t)row * 128 + kg * 4];
        *(uint2*)&xs[r * SR + kg * 2] = make_uint2(pkh2(v.x, v.y), pkh2(v.z, v.w));
    }
    // W: plain [k][n] halves, n-contiguous, stride SR words per k row
#pragma unroll
    for (int L = tid; L < 4096; L += 256) {
        int k  = L >> 5;
        int ng = L & 31;
        float4 v = *(const float4*)&W[(size_t)k * 128 + ng * 4];
        *(uint2*)&wh[k * SR + ng * 2] = make_uint2(pkh2(v.x, v.y), pkh2(v.z, v.w));
    }
    __syncthreads();

    float acc[16][4];
#pragma unroll
    for (int j = 0; j < 16; j++)
#pragma unroll
        for (int i = 0; i < 4; i++) acc[j][i] = 0.f;

    uint32_t sbase = (uint32_t)__cvta_generic_to_shared(sm);
    // A ldmatrix: lanes 0-7 rows g (mat a0), 8-15 rows g+8 (a1), 16-23 k2+4 (a2), 24-31 (a3)
    uint32_t a_addr = sbase + (((w * 16 + (lane & 15)) * SR + ((lane >> 4) << 2)) << 2);
    // B ldmatrix.trans: rows k = 16m + (lane&15); n-chunk +8 halves for lanes>=16
    uint32_t b_addr = sbase + ((128 * SR + (lane & 15) * SR + ((lane >> 4) << 2)) << 2);

#pragma unroll
    for (int m = 0; m < 8; m++) {
        uint32_t a0, a1, a2, a3;
        ldsm_x4(a0, a1, a2, a3, a_addr + m * 32);          // +8 words per m
        uint32_t bb = b_addr + m * 16 * SR * 4;            // +16 k-rows per m
#pragma unroll
        for (int j = 0; j < 16; j += 2) {
            uint32_t b0, b1, b2, b3;
            ldsm_x4t(b0, b1, b2, b3, bb + j * 16);         // +4 words per j
            mma_f16(acc[j][0],   acc[j][1],   acc[j][2],   acc[j][3],
                    a0, a1, a2, a3, b0, b1);
            mma_f16(acc[j+1][0], acc[j+1][1], acc[j+1][2], acc[j+1][3],
                    a0, a1, a2, a3, b2, b3);
        }
    }

    int rowA = r0 + w * 16 + g;
#pragma unroll
    for (int j = 0; j < 16; j++) {
        if (rowA < M)
            C[(size_t)rowA * 64 + j * 4 + t4] = pkh2(acc[j][0], acc[j][1]);
        if (rowA + 8 < M)
            C[(size_t)(rowA + 8) * 64 + j * 4 + t4] = pkh2(acc[j][2], acc[j][3]);
    }
}

// ---------------- single-shot fp16 GEMM (ldmatrix): [M,128]half @ [128,40] ----
__global__ __launch_bounds__(256) void gemm40_f16_kernel(
    const uint32_t* __restrict__ Ah, const float* __restrict__ W,
    uint32_t* __restrict__ C, int M)
{
    extern __shared__ uint32_t sm[];
    uint32_t* xs = sm;
    uint32_t* wh = sm + 128 * SR;

    int tid  = threadIdx.x;
    int w    = tid >> 5;
    int lane = tid & 31;
    int g    = lane >> 2;
    int t4   = lane & 3;
    int r0   = blockIdx.x * 128;

    // A (already half2): 128 rows x 16 uint4 groups
#pragma unroll
    for (int L = tid; L < 2048; L += 256) {
        int r  = L >> 4;
        int kq = L & 15;
        int row = r0 + r;
        uint4 v = make_uint4(0u, 0u, 0u, 0u);
        if (row < M)
            v = *(const uint4*)&Ah[(size_t)row * 64 + kq * 4];
        *(uint4*)&xs[r * SR + kq * 4] = v;
    }
    // zero the wh pad words the j=4..5 ldmatrix reads touch (cols 40..47)
#pragma unroll
    for (int L = tid; L < 512; L += 256) {
        int k = L >> 2;
        wh[k * SR + 20 + (L & 3)] = 0u;
    }
    // W2: plain [k][n<40] halves
#pragma unroll
    for (int L = tid; L < 1280; L += 256) {
        int k  = L / 10;
        int ng = L % 10;
        float4 v = *(const float4*)&W[(size_t)k * 40 + ng * 4];
        *(uint2*)&wh[k * SR + ng * 2] = make_uint2(pkh2(v.x, v.y), pkh2(v.z, v.w));
    }
    __syncthreads();

    float acc[6][4];
#pragma unroll
    for (int j = 0; j < 6; j++)
#pragma unroll
        for (int i = 0; i < 4; i++) acc[j][i] = 0.f;

    uint32_t sbase = (uint32_t)__cvta_generic_to_shared(sm);
    uint32_t a_addr = sbase + (((w * 16 + (lane & 15)) * SR + ((lane >> 4) << 2)) << 2);
    uint32_t b_addr = sbase + ((128 * SR + (lane & 15) * SR + ((lane >> 4) << 2)) << 2);

#pragma unroll
    for (int m = 0; m < 8; m++) {
        uint32_t a0, a1, a2, a3;
        ldsm_x4(a0, a1, a2, a3, a_addr + m * 32);
        uint32_t bb = b_addr + m * 16 * SR * 4;
#pragma unroll
        for (int j = 0; j < 6; j += 2) {
            uint32_t b0, b1, b2, b3;
            ldsm_x4t(b0, b1, b2, b3, bb + j * 16);
            mma_f16(acc[j][0],   acc[j][1],   acc[j][2],   acc[j][3],
                    a0, a1, a2, a3, b0, b1);
            mma_f16(acc[j+1][0], acc[j+1][1], acc[j+1][2], acc[j+1][3],
                    a0, a1, a2, a3, b2, b3);
        }
    }

    int rowA = r0 + w * 16 + g;
#pragma unroll
    for (int j = 0; j < 5; j++) {
        if (rowA < M)
            C[(size_t)rowA * 20 + j * 4 + t4] = pkh2(acc[j][0], acc[j][1]);
        if (rowA + 8 < M)
            C[(size_t)(rowA + 8) * 20 + j * 4 + t4] = pkh2(acc[j][2], acc[j][3]);
    }
}

// ---------------- gather layer 1 (C=128, fp16): warp per node -----------------
__global__ __launch_bounds__(256) void gather128_kernel(const float* __restrict__ b1) {
    int w = (blockIdx.x * blockDim.x + threadIdx.x) >> 5;
    if (w >= NNODES) return;
    int lane = threadIdx.x & 31;

    int start = g_rowstart[w];
    int end   = g_rowstart[w + 1];

    const uint2* __restrict__ h = (const uint2*)g_h1h;
    float4 acc = make_float4(0.f, 0.f, 0.f, 0.f);

    int j = start;
    for (; j + 3 < end; j += 4) {
        int   s0 = __ldg(&g_csr_src[j]);
        int   s1 = __ldg(&g_csr_src[j + 1]);
        int   s2 = __ldg(&g_csr_src[j + 2]);
        int   s3 = __ldg(&g_csr_src[j + 3]);
        float n0 = __ldg(&g_csr_nrm[j]);
        float n1 = __ldg(&g_csr_nrm[j + 1]);
        float n2 = __ldg(&g_csr_nrm[j + 2]);
        float n3 = __ldg(&g_csr_nrm[j + 3]);
        uint2 u0 = h[(size_t)s0 * 32 + lane];
        uint2 u1 = h[(size_t)s1 * 32 + lane];
        uint2 u2 = h[(size_t)s2 * 32 + lane];
        uint2 u3 = h[(size_t)s3 * 32 + lane];
        float2 a, b;
        a = h2f2(u0.x); b = h2f2(u0.y);
        acc.x = fmaf(n0, a.x, acc.x); acc.y = fmaf(n0, a.y, acc.y);
        acc.z = fmaf(n0, b.x, acc.z); acc.w = fmaf(n0, b.y, acc.w);
        a = h2f2(u1.x); b = h2f2(u1.y);
        acc.x = fmaf(n1, a.x, acc.x); acc.y = fmaf(n1, a.y, acc.y);
        acc.z = fmaf(n1, b.x, acc.z); acc.w = fmaf(n1, b.y, acc.w);
        a = h2f2(u2.x); b = h2f2(u2.y);
        acc.x = fmaf(n2, a.x, acc.x); acc.y = fmaf(n2, a.y, acc.y);
        acc.z = fmaf(n2, b.x, acc.z); acc.w = fmaf(n2, b.y, acc.w);
        a = h2f2(u3.x); b = h2f2(u3.y);
        acc.x = fmaf(n3, a.x, acc.x); acc.y = fmaf(n3, a.y, acc.y);
        acc.z = fmaf(n3, b.x, acc.z); acc.w = fmaf(n3, b.y, acc.w);
    }
    for (; j < end; ++j) {
        int   s0 = __ldg(&g_csr_src[j]);
        float n0 = __ldg(&g_csr_nrm[j]);
        uint2 u0 = h[(size_t)s0 * 32 + lane];
        float2 a = h2f2(u0.x), b = h2f2(u0.y);
        acc.x = fmaf(n0, a.x, acc.x); acc.y = fmaf(n0, a.y, acc.y);
        acc.z = fmaf(n0, b.x, acc.z); acc.w = fmaf(n0, b.y, acc.w);
    }

    float di = g_dinv[w];
    float d2 = di * di;
    uint2 us = h[(size_t)w * 32 + lane];
    float2 ha = h2f2(us.x), hb = h2f2(us.y);
    float4 bb = ((const float4*)b1)[lane];
    float rx = fmaxf(fmaf(ha.x, d2, acc.x) + bb.x, 0.f);
    float ry = fmaxf(fmaf(ha.y, d2, acc.y) + bb.y, 0.f);
    float rz = fmaxf(fmaf(hb.x, d2, acc.z) + bb.z, 0.f);
    float rw = fmaxf(fmaf(hb.y, d2, acc.w) + bb.w, 0.f);
    uint2 o;
    o.x = pkh2(rx, ry);
    o.y = pkh2(rz, rw);
    ((uint2*)g_h1bh)[(size_t)w * 32 + lane] = o;
}

// ---------------- gather layer 2 (C=40, fp16): two nodes per warp -------------
__global__ __launch_bounds__(256) void gather40_kernel(const float* __restrict__ b2,
                                                       float* __restrict__ out) {
    int w = (blockIdx.x * blockDim.x + threadIdx.x) >> 5;
    int lane = threadIdx.x & 31;
    int node = w * 2 + (lane >> 4);
    if (node >= NNODES) return;
    int sub = lane & 15;
    bool active = sub < 10;

    int start = g_rowstart[node];
    int end   = g_rowstart[node + 1];

    const uint2* __restrict__ h = (const uint2*)g_h2h;
    float4 acc = make_float4(0.f, 0.f, 0.f, 0.f);

    int j = start;
    for (; j + 3 < end; j += 4) {
        int   s0 = __ldg(&g_csr_src[j]);
        int   s1 = __ldg(&g_csr_src[j + 1]);
        int   s2 = __ldg(&g_csr_src[j + 2]);
        int   s3 = __ldg(&g_csr_src[j + 3]);
        float n0 = __ldg(&g_csr_nrm[j]);
        float n1 = __ldg(&g_csr_nrm[j + 1]);
        float n2 = __ldg(&g_csr_nrm[j + 2]);
        float n3 = __ldg(&g_csr_nrm[j + 3]);
        if (active) {
            uint2 u0 = h[(size_t)s0 * 10 + sub];
            uint2 u1 = h[(size_t)s1 * 10 + sub];
            uint2 u2 = h[(size_t)s2 * 10 + sub];
            uint2 u3 = h[(size_t)s3 * 10 + sub];
            float2 a, b;
            a = h2f2(u0.x); b = h2f2(u0.y);
            acc.x = fmaf(n0, a.x, acc.x); acc.y = fmaf(n0, a.y, acc.y);
            acc.z = fmaf(n0, b.x, acc.z); acc.w = fmaf(n0, b.y, acc.w);
            a = h2f2(u1.x); b = h2f2(u1.y);
            acc.x = fmaf(n1, a.x, acc.x); acc.y = fmaf(n1, a.y, acc.y);
            acc.z = fmaf(n1, b.x, acc.z); acc.w = fmaf(n1, b.y, acc.w);
            a = h2f2(u2.x); b = h2f2(u2.y);
            acc.x = fmaf(n2, a.x, acc.x); acc.y = fmaf(n2, a.y, acc.y);
            acc.z = fmaf(n2, b.x, acc.z); acc.w = fmaf(n2, b.y, acc.w);
            a = h2f2(u3.x); b = h2f2(u3.y);
            acc.x = fmaf(n3, a.x, acc.x); acc.y = fmaf(n3, a.y, acc.y);
            acc.z = fmaf(n3, b.x, acc.z); acc.w = fmaf(n3, b.y, acc.w);
        }
    }
    for (; j < end; ++j) {
        int   s0 = __ldg(&g_csr_src[j]);
        float n0 = __ldg(&g_csr_nrm[j]);
        if (active) {
            uint2 u0 = h[(size_t)s0 * 10 + sub];
            float2 a = h2f2(u0.x), b = h2f2(u0.y);
            acc.x = fmaf(n0, a.x, acc.x); acc.y = fmaf(n0, a.y, acc.y);
            acc.z = fmaf(n0, b.x, acc.z); acc.w = fmaf(n0, b.y, acc.w);
        }
    }

    if (active) {
        float di = g_dinv[node];
        float d2 = di * di;
        uint2 us = h[(size_t)node * 10 + sub];
        float2 ha = h2f2(us.x), hb = h2f2(us.y);
        float4 bb = ((const float4*)b2)[sub];
        float4 r;
        r.x = fmaf(ha.x, d2, acc.x) + bb.x;
        r.y = fmaf(ha.y, d2, acc.y) + bb.y;
        r.z = fmaf(hb.x, d2, acc.z) + bb.z;
        r.w = fmaf(hb.y, d2, acc.w) + bb.w;
        *(float4*)&out[(size_t)node * 40 + sub * 4] = r;
    }
}

// -----------------------------------------------------------------------------
extern "C" void kernel_launch(void* const* d_in, const int* in_sizes, int n_in,
                              void* d_out, int out_size) {
    const float* x   = (const float*)d_in[0];
    const int*   ei  = (const int*)  d_in[1];
    const float* W1  = (const float*)d_in[2];
    const float* b1  = (const float*)d_in[3];
    const float* W2  = (const float*)d_in[4];
    const float* b2  = (const float*)d_in[5];
    float* out = (float*)d_out;

    static bool s_init = false;
    static cudaStream_t s2;
    static cudaEvent_t evA, evB;
    if (!s_init) {   // host-side setup on first (uncaptured) call only
        cudaFuncSetAttribute(gemm128_f16_kernel,
                             cudaFuncAttributeMaxDynamicSharedMemorySize, GEMM_SMEM);
        cudaFuncSetAttribute(gemm40_f16_kernel,
                             cudaFuncAttributeMaxDynamicSharedMemorySize, GEMM_SMEM);
        cudaStreamCreateWithFlags(&s2, cudaStreamNonBlocking);
        cudaEventCreateWithFlags(&evA, cudaEventDisableTiming);
        cudaEventCreateWithFlags(&evB, cudaEventDisableTiming);
        s_init = true;
    }

    uint32_t* h1_p;  cudaGetSymbolAddress((void**)&h1_p,  g_h1h);
    uint32_t* h1b_p; cudaGetSymbolAddress((void**)&h1b_p, g_h1bh);
    uint32_t* h2_p;  cudaGetSymbolAddress((void**)&h2_p,  g_h2h);

    // ---- fork: CSR build on s2, concurrent with gemm128 on main stream ----
    cudaEventRecord(evA, 0);
    cudaStreamWaitEvent(s2, evA, 0);
    degree_kernel<<<(NEDGES + 255) / 256, 256, 0, s2>>>(ei);
    scan_fused_kernel<<<NB, 256, 0, s2>>>();
    csrfill_kernel<<<(NEDGES + 255) / 256, 256, 0, s2>>>(ei);
    cudaEventRecord(evB, s2);

    gemm128_f16_kernel<<<(NNODES + 127) / 128, 256, GEMM_SMEM>>>(x, W1, h1_p, NNODES);

    // ---- join, then the dependent chain ----
    cudaStreamWaitEvent(0, evB, 0);
    gather128_kernel<<<(NNODES * 32 + 255) / 256, 256>>>(b1);
    gemm40_f16_kernel<<<(NNODES + 127) / 128, 256, GEMM_SMEM>>>(h1b_p, W2, h2_p, NNODES);
    gather40_kernel<<<((NNODES + 1) / 2 * 32 + 255) / 256, 256>>>(b2, out);
}